// round 1
// baseline (speedup 1.0000x reference)
#include <cuda_runtime.h>
#include <stdint.h>

// Hash-grid trilinear interpolation.
// BUCKETS = 1<<22, RES = 1/1024, D = 8 features (fp32).
// vid = (bx*1 + by*2654435761 + bz*805459861) mod 2^22   (uint32 wraparound)
// out[i] = sum_c w_c * feat[vid_c]

#define BUCKETS_MASK ((1u << 22) - 1u)
#define P1 1u
#define P2 2654435761u
#define P3 805459861u

__global__ void __launch_bounds__(256) hashgrid_interp_kernel(
    const float* __restrict__ pts,          // (N,3)
    const float4* __restrict__ vf,          // (BUCKETS, 8) viewed as (BUCKETS*2) float4
    float4* __restrict__ out,               // (N, 8) viewed as (N*2) float4
    int n)
{
    int i = blockIdx.x * blockDim.x + threadIdx.x;
    if (i >= n) return;

    // Load point (coalesced-ish: warp reads 384 contiguous bytes)
    float x = pts[3 * i + 0];
    float y = pts[3 * i + 1];
    float z = pts[3 * i + 2];

    // Continuous grid coords (RES = 1/1024)
    float qx = x * 1024.0f;
    float qy = y * 1024.0f;
    float qz = z * 1024.0f;

    float bxf = floorf(qx);
    float byf = floorf(qy);
    float bzf = floorf(qz);

    float fx = qx - bxf;
    float fy = qy - byf;
    float fz = qz - bzf;

    uint32_t bx = (uint32_t)(int)bxf;
    uint32_t by = (uint32_t)(int)byf;
    uint32_t bz = (uint32_t)(int)bzf;

    // Base hash; corner hashes are additive prime offsets (uint32 wraparound)
    uint32_t h = bx * P1 + by * P2 + bz * P3;

    uint32_t vid[8];
    vid[0] = (h)                & BUCKETS_MASK;   // (0,0,0)
    vid[1] = (h + P1)           & BUCKETS_MASK;   // (1,0,0)
    vid[2] = (h + P2)           & BUCKETS_MASK;   // (0,1,0)
    vid[3] = (h + P1 + P2)      & BUCKETS_MASK;   // (1,1,0)
    vid[4] = (h + P3)           & BUCKETS_MASK;   // (0,0,1)
    vid[5] = (h + P1 + P3)      & BUCKETS_MASK;   // (1,0,1)
    vid[6] = (h + P2 + P3)      & BUCKETS_MASK;   // (0,1,1)
    vid[7] = (h + P1 + P2 + P3) & BUCKETS_MASK;   // (1,1,1)

    // Trilinear weights, corner order matches CORNER_OFFSETS
    float gx = 1.0f - fx, gy = 1.0f - fy, gz = 1.0f - fz;
    float w[8];
    w[0] = gx * gy * gz;
    w[1] = fx * gy * gz;
    w[2] = gx * fy * gz;
    w[3] = fx * fy * gz;
    w[4] = gx * gy * fz;
    w[5] = fx * gy * fz;
    w[6] = gx * fy * fz;
    w[7] = fx * fy * fz;

    // Issue all 16 gathers first (MLP = 16) to hide L2/DRAM latency
    float4 f0[8], f1[8];
#pragma unroll
    for (int c = 0; c < 8; c++) {
        const float4* p = vf + (size_t)vid[c] * 2;
        f0[c] = __ldg(p);
        f1[c] = __ldg(p + 1);
    }

    float4 a0 = make_float4(0.f, 0.f, 0.f, 0.f);
    float4 a1 = make_float4(0.f, 0.f, 0.f, 0.f);
#pragma unroll
    for (int c = 0; c < 8; c++) {
        float wc = w[c];
        a0.x = fmaf(wc, f0[c].x, a0.x);
        a0.y = fmaf(wc, f0[c].y, a0.y);
        a0.z = fmaf(wc, f0[c].z, a0.z);
        a0.w = fmaf(wc, f0[c].w, a0.w);
        a1.x = fmaf(wc, f1[c].x, a1.x);
        a1.y = fmaf(wc, f1[c].y, a1.y);
        a1.z = fmaf(wc, f1[c].z, a1.z);
        a1.w = fmaf(wc, f1[c].w, a1.w);
    }

    out[2 * (size_t)i + 0] = a0;
    out[2 * (size_t)i + 1] = a1;
}

extern "C" void kernel_launch(void* const* d_in, const int* in_sizes, int n_in,
                              void* d_out, int out_size)
{
    const float*  pts = (const float*)d_in[0];
    const float4* vf  = (const float4*)d_in[1];
    // d_in[2] = primes (constants baked into the kernel)
    float4* out = (float4*)d_out;

    int n = in_sizes[0] / 3;   // number of points

    int block = 256;
    int grid = (n + block - 1) / block;
    hashgrid_interp_kernel<<<grid, block>>>(pts, vf, out, n);
}